// round 1
// baseline (speedup 1.0000x reference)
#include <cuda_runtime.h>
#include <cuda_bf16.h>

// Problem constants
#define BATCH 8
#define CI    64
#define CO    128
#define HH    128
#define WW    128
#define HW    (HH*WW)          // 16384

// Scratch: y = conv1x1(x) output, [B][CO][H][W] fp32 = 64 MiB
__device__ float g_y[BATCH * CO * HW];

// ---------------------------------------------------------------------------
// Kernel 1: 1x1 conv as GEMM.  Per CTA: 128 output channels x 128 pixels.
// blockDim = 256 (16x16), each thread computes an 8(o) x 8(p) microtile.
// Dynamic smem: Ws[i][o] (64x128 f32, transposed Wc) + Xs[i][p] (64x128 f32).
// ---------------------------------------------------------------------------
__global__ void conv1x1_kernel(const float* __restrict__ x,
                               const float* __restrict__ Wc,
                               const float* __restrict__ bc)
{
    extern __shared__ float sm[];
    float* Ws = sm;            // 64*128
    float* Xs = sm + 64 * 128; // 64*128

    const int b  = blockIdx.y;
    const int p0 = blockIdx.x * 128;
    const int tid = threadIdx.x;

    // Load Wc transposed: Ws[i*128 + o] = Wc[o*64 + i]
    for (int idx = tid; idx < 64 * 128; idx += 256) {
        int i = idx >> 7;
        int o = idx & 127;
        Ws[idx] = Wc[o * CI + i];
    }
    // Load x tile: Xs[i*128 + p] = x[b][i][p0+p]   (float4, coalesced)
    {
        const float4* xb4 = reinterpret_cast<const float4*>(x + (size_t)b * CI * HW);
        float4* Xs4 = reinterpret_cast<float4*>(Xs);
        // 64*128 floats = 2048 float4
        for (int idx = tid; idx < 2048; idx += 256) {
            int i  = idx >> 5;          // 32 float4 per row
            int p4 = idx & 31;
            Xs4[idx] = xb4[i * (HW / 4) + (p0 >> 2) + p4];
        }
    }
    __syncthreads();

    const int tx = tid & 15;   // pixel group
    const int ty = tid >> 4;   // output-channel group

    float acc[8][8];
#pragma unroll
    for (int a = 0; a < 8; ++a)
#pragma unroll
        for (int c = 0; c < 8; ++c) acc[a][c] = 0.0f;

    const float4* Ws4 = reinterpret_cast<const float4*>(Ws);
    const float4* Xs4 = reinterpret_cast<const float4*>(Xs);

#pragma unroll 8
    for (int i = 0; i < 64; ++i) {
        float4 w0 = Ws4[i * 32 + ty * 2];
        float4 w1 = Ws4[i * 32 + ty * 2 + 1];
        float4 v0 = Xs4[i * 32 + tx * 2];
        float4 v1 = Xs4[i * 32 + tx * 2 + 1];
        float wv[8] = {w0.x, w0.y, w0.z, w0.w, w1.x, w1.y, w1.z, w1.w};
        float xv[8] = {v0.x, v0.y, v0.z, v0.w, v1.x, v1.y, v1.z, v1.w};
#pragma unroll
        for (int oo = 0; oo < 8; ++oo)
#pragma unroll
            for (int pp = 0; pp < 8; ++pp)
                acc[oo][pp] = fmaf(wv[oo], xv[pp], acc[oo][pp]);
    }

    // Write y with bias
    const int o0 = ty * 8;
    const int pg = p0 + tx * 8;
    float* yb = g_y + (size_t)b * CO * HW;
#pragma unroll
    for (int oo = 0; oo < 8; ++oo) {
        float bv = bc[o0 + oo];
        float4 r0, r1;
        r0.x = acc[oo][0] + bv; r0.y = acc[oo][1] + bv;
        r0.z = acc[oo][2] + bv; r0.w = acc[oo][3] + bv;
        r1.x = acc[oo][4] + bv; r1.y = acc[oo][5] + bv;
        r1.z = acc[oo][6] + bv; r1.w = acc[oo][7] + bv;
        float4* dst = reinterpret_cast<float4*>(yb + (size_t)(o0 + oo) * HW + pg);
        dst[0] = r0;
        dst[1] = r1;
    }
}

// ---------------------------------------------------------------------------
// Kernel 2: 3x3 local attention.
// Per CTA: 16x16 pixel tile; smem holds 18x18 halo of y, layout [c][pix]
// (pix = hh*18+ww), stride 324 floats -> 165888 B dynamic smem.
// Thread = one pixel. Pass 1: 9 scores (dot over 128 c). Softmax.
// Pass 2: weighted sum per channel, store fp32 out.
// ---------------------------------------------------------------------------
#define TS    16
#define HALO  18
#define NPIX  (HALO*HALO)      // 324

__global__ void attn3x3_kernel(float* __restrict__ out)
{
    extern __shared__ float ys[]; // [128][324]

    const int b  = blockIdx.z;
    const int h0 = blockIdx.y * TS;
    const int w0 = blockIdx.x * TS;
    const int tid = threadIdx.x;  // 256

    const float* yb = g_y + (size_t)b * CO * HW;

    // Load halo (zero-padded at image border)
    for (int c = 0; c < CO; ++c) {
        const float* yc = yb + (size_t)c * HW;
        float* row = ys + c * NPIX;
        for (int pix = tid; pix < NPIX; pix += 256) {
            int hh = pix / HALO;
            int ww2 = pix - hh * HALO;
            int gh = h0 - 1 + hh;
            int gw = w0 - 1 + ww2;
            float v = 0.0f;
            if ((unsigned)gh < HH && (unsigned)gw < WW) v = yc[gh * WW + gw];
            row[pix] = v;
        }
    }
    __syncthreads();

    const int lw = tid & 15;
    const int lh = tid >> 4;

    // neighbor pixel indices in halo coords
    int pn[9];
#pragma unroll
    for (int n = 0; n < 9; ++n) {
        int di = n / 3, dj = n - (n / 3) * 3;
        pn[n] = (lh + di) * HALO + (lw + dj);
    }

    // Pass 1: scores
    float s[9];
#pragma unroll
    for (int n = 0; n < 9; ++n) s[n] = 0.0f;

    for (int c = 0; c < CO; ++c) {
        const float* row = ys + c * NPIX;
        float mid = row[pn[4]];
#pragma unroll
        for (int n = 0; n < 9; ++n)
            s[n] = fmaf(row[pn[n]], mid, s[n]);
    }

    const float scale = 0.08838834764831845f; // 1/sqrt(128)
    float mx = s[0] * scale;
#pragma unroll
    for (int n = 1; n < 9; ++n) mx = fmaxf(mx, s[n] * scale);

    float a[9];
    float den = 0.0f;
#pragma unroll
    for (int n = 0; n < 9; ++n) {
        a[n] = __expf(s[n] * scale - mx);
        den += a[n];
    }
    float inv = 1.0f / den;
#pragma unroll
    for (int n = 0; n < 9; ++n) a[n] *= inv;

    // Pass 2: weighted sum per channel, write out
    float* ob = out + (size_t)b * CO * HW + (size_t)(h0 + lh) * WW + (w0 + lw);
    for (int c = 0; c < CO; ++c) {
        const float* row = ys + c * NPIX;
        float o = 0.0f;
#pragma unroll
        for (int n = 0; n < 9; ++n)
            o = fmaf(a[n], row[pn[n]], o);
        ob[(size_t)c * HW] = o;
    }
}

// ---------------------------------------------------------------------------
extern "C" void kernel_launch(void* const* d_in, const int* in_sizes, int n_in,
                              void* d_out, int out_size)
{
    // Identify inputs by element count (robust to ordering)
    const float* x  = nullptr;
    const float* Wc = nullptr;
    const float* bc = nullptr;
    for (int i = 0; i < n_in; ++i) {
        if (in_sizes[i] == BATCH * CI * HW) x  = (const float*)d_in[i];
        else if (in_sizes[i] == CO * CI)    Wc = (const float*)d_in[i];
        else if (in_sizes[i] == CO)         bc = (const float*)d_in[i];
    }
    float* out = (float*)d_out;

    static const int conv_smem = 64 * 128 * 2 * sizeof(float);   // 65536
    static const int attn_smem = CO * NPIX * sizeof(float);      // 165888

    cudaFuncSetAttribute(conv1x1_kernel,
                         cudaFuncAttributeMaxDynamicSharedMemorySize, conv_smem);
    cudaFuncSetAttribute(attn3x3_kernel,
                         cudaFuncAttributeMaxDynamicSharedMemorySize, attn_smem);

    conv1x1_kernel<<<dim3(HW / 128, BATCH), 256, conv_smem>>>(x, Wc, bc);
    attn3x3_kernel<<<dim3(WW / TS, HH / TS, BATCH), 256, attn_smem>>>(out);
}

// round 2
// speedup vs baseline: 3.8276x; 3.8276x over previous
#include <cuda_runtime.h>
#include <cuda_bf16.h>

// Problem constants
#define BATCH 8
#define CI    64
#define CO    128
#define HH    128
#define WW    128
#define HW    (HH*WW)          // 16384

// Scratch: y = conv1x1(x), PIXEL-MAJOR layout: y[b][p][c], p=h*W+w. 64 MiB fp32.
__device__ float g_y[BATCH * HW * CO];

// ---------------------------------------------------------------------------
// Kernel 1: 1x1 conv as GEMM.  Per CTA: 128 output channels x 128 pixels.
// blockDim=256: tx (0..15) = channel group, ty (0..15) = pixel group.
// Thread computes 8 pixels x 8 channels; channels are {tx*4..tx*4+3} and
// {64+tx*4..64+tx*4+3} so stores to pixel-major y are coalesced float4s.
// ---------------------------------------------------------------------------
__global__ void conv1x1_kernel(const float* __restrict__ x,
                               const float* __restrict__ Wc,
                               const float* __restrict__ bc)
{
    extern __shared__ float sm[];
    float* Ws = sm;            // [i][o] 64*128 (Wc transposed)
    float* Xs = sm + 64 * 128; // [i][p] 64*128

    const int b  = blockIdx.y;
    const int p0 = blockIdx.x * 128;
    const int tid = threadIdx.x;

    // Load Wc transposed: Ws[i*128 + o] = Wc[o*64 + i]
    for (int idx = tid; idx < 64 * 128; idx += 256) {
        int i = idx >> 7;
        int o = idx & 127;
        Ws[idx] = Wc[o * CI + i];
    }
    // Load x tile: Xs[i*128 + p] = x[b][i][p0+p]   (float4, coalesced)
    {
        const float4* xb4 = reinterpret_cast<const float4*>(x + (size_t)b * CI * HW);
        float4* Xs4 = reinterpret_cast<float4*>(Xs);
        for (int idx = tid; idx < 2048; idx += 256) {
            int i  = idx >> 5;
            int p4 = idx & 31;
            Xs4[idx] = xb4[i * (HW / 4) + (p0 >> 2) + p4];
        }
    }
    __syncthreads();

    const int tx = tid & 15;   // channel group
    const int ty = tid >> 4;   // pixel group

    // acc[pp][k]: k 0..3 -> channel tx*4+k ; k 4..7 -> channel 64+tx*4+(k-4)
    float acc[8][8];
#pragma unroll
    for (int a = 0; a < 8; ++a)
#pragma unroll
        for (int c = 0; c < 8; ++c) acc[a][c] = 0.0f;

    const float4* Ws4 = reinterpret_cast<const float4*>(Ws);
    const float4* Xs4 = reinterpret_cast<const float4*>(Xs);

#pragma unroll 8
    for (int i = 0; i < 64; ++i) {
        float4 w0 = Ws4[i * 32 + tx];        // channels tx*4..+3
        float4 w1 = Ws4[i * 32 + 16 + tx];   // channels 64+tx*4..+3
        float4 v0 = Xs4[i * 32 + ty * 2];    // pixels ty*8..+3
        float4 v1 = Xs4[i * 32 + ty * 2 + 1];// pixels ty*8+4..+7
        float wv[8] = {w0.x, w0.y, w0.z, w0.w, w1.x, w1.y, w1.z, w1.w};
        float xv[8] = {v0.x, v0.y, v0.z, v0.w, v1.x, v1.y, v1.z, v1.w};
#pragma unroll
        for (int pp = 0; pp < 8; ++pp)
#pragma unroll
            for (int k = 0; k < 8; ++k)
                acc[pp][k] = fmaf(xv[pp], wv[k], acc[pp][k]);
    }

    // Bias
    float bv[8];
#pragma unroll
    for (int k = 0; k < 4; ++k) {
        bv[k]     = bc[tx * 4 + k];
        bv[k + 4] = bc[64 + tx * 4 + k];
    }

    // Write y pixel-major: y[(b*HW + p)*128 + c]
    float* yb = g_y + ((size_t)b * HW + p0) * CO;
#pragma unroll
    for (int pp = 0; pp < 8; ++pp) {
        float* dst = yb + (size_t)(ty * 8 + pp) * CO;
        float4 r0, r1;
        r0.x = acc[pp][0] + bv[0]; r0.y = acc[pp][1] + bv[1];
        r0.z = acc[pp][2] + bv[2]; r0.w = acc[pp][3] + bv[3];
        r1.x = acc[pp][4] + bv[4]; r1.y = acc[pp][5] + bv[5];
        r1.z = acc[pp][6] + bv[6]; r1.w = acc[pp][7] + bv[7];
        reinterpret_cast<float4*>(dst + tx * 4)[0]      = r0;
        reinterpret_cast<float4*>(dst + 64 + tx * 4)[0] = r1;
    }
}

// ---------------------------------------------------------------------------
// Kernel 2: 3x3 local attention, warp-per-pixel, register resident.
// CTA = 256 threads = 8 warps = 8 consecutive pixels in one image row.
// Lane l owns channels 4l..4l+3. 9 neighbor vectors loaded once (LDG.128,
// fully coalesced), kept in registers; center = v[4].
// 9 warp butterfly reductions -> softmax -> weighted sum -> smem transpose
// stage -> coalesced channel-major store.
// ---------------------------------------------------------------------------
__global__ void attn3x3_kernel(float* __restrict__ out)
{
    __shared__ float so[8 * CO];  // [pix][c]

    const int tid  = threadIdx.x;
    const int wid  = tid >> 5;
    const int lane = tid & 31;

    const int g = blockIdx.x * 8 + wid;   // global pixel id
    const int b = g >> 14;                // / HW
    const int p = g & (HW - 1);
    const int h = p >> 7;                 // / WW
    const int w = p & (WW - 1);

    const float* ybase = g_y + ((size_t)b * HW) * CO + lane * 4;

    // Load 9 neighbor channel-vectors (4 channels per lane) into registers
    float4 v[9];
#pragma unroll
    for (int n = 0; n < 9; ++n) {
        int gh = h + n / 3 - 1;
        int gw = w + n % 3 - 1;
        if ((unsigned)gh < HH && (unsigned)gw < WW) {
            v[n] = *reinterpret_cast<const float4*>(ybase + (size_t)(gh * WW + gw) * CO);
        } else {
            v[n] = make_float4(0.f, 0.f, 0.f, 0.f);
        }
    }

    // Partial dot products with center (v[4])
    float s[9];
#pragma unroll
    for (int n = 0; n < 9; ++n) {
        s[n] = v[n].x * v[4].x + v[n].y * v[4].y
             + v[n].z * v[4].z + v[n].w * v[4].w;
    }

    // Warp butterfly reductions (all lanes end with full sums)
#pragma unroll
    for (int off = 16; off > 0; off >>= 1) {
#pragma unroll
        for (int n = 0; n < 9; ++n)
            s[n] += __shfl_xor_sync(0xffffffffu, s[n], off);
    }

    // Softmax over the 9 scores
    const float scale = 0.08838834764831845f; // 1/sqrt(128)
    float mx = s[0];
#pragma unroll
    for (int n = 1; n < 9; ++n) mx = fmaxf(mx, s[n]);
    float a[9], den = 0.f;
#pragma unroll
    for (int n = 0; n < 9; ++n) {
        a[n] = __expf((s[n] - mx) * scale);
        den += a[n];
    }
    float inv = 1.0f / den;

    // Weighted sum from registers
    float4 o = make_float4(0.f, 0.f, 0.f, 0.f);
#pragma unroll
    for (int n = 0; n < 9; ++n) {
        float an = a[n] * inv;
        o.x = fmaf(an, v[n].x, o.x);
        o.y = fmaf(an, v[n].y, o.y);
        o.z = fmaf(an, v[n].z, o.z);
        o.w = fmaf(an, v[n].w, o.w);
    }

    // Stage [pix][c] in smem (conflict-free float4 stores)
    *reinterpret_cast<float4*>(&so[wid * CO + lane * 4]) = o;
    __syncthreads();

    // Transposed, fully-coalesced channel-major store:
    // thread tid: c = tid>>1, pixel offset q = (tid&1)*4, writes float4 of
    // 4 consecutive pixels for channel c.
    {
        const int c = tid >> 1;
        const int q = (tid & 1) * 4;
        float4 r;
        r.x = so[(q + 0) * CO + c];
        r.y = so[(q + 1) * CO + c];
        r.z = so[(q + 2) * CO + c];
        r.w = so[(q + 3) * CO + c];
        const int pbase = (blockIdx.x * 8) & (HW - 1);
        float* dst = out + ((size_t)b * CO + c) * HW + pbase + q;
        *reinterpret_cast<float4*>(dst) = r;
    }
}

// ---------------------------------------------------------------------------
extern "C" void kernel_launch(void* const* d_in, const int* in_sizes, int n_in,
                              void* d_out, int out_size)
{
    const float* x  = nullptr;
    const float* Wc = nullptr;
    const float* bc = nullptr;
    for (int i = 0; i < n_in; ++i) {
        if (in_sizes[i] == BATCH * CI * HW) x  = (const float*)d_in[i];
        else if (in_sizes[i] == CO * CI)    Wc = (const float*)d_in[i];
        else if (in_sizes[i] == CO)         bc = (const float*)d_in[i];
    }
    float* out = (float*)d_out;

    static const int conv_smem = 64 * 128 * 2 * sizeof(float);   // 65536

    cudaFuncSetAttribute(conv1x1_kernel,
                         cudaFuncAttributeMaxDynamicSharedMemorySize, conv_smem);

    conv1x1_kernel<<<dim3(HW / 128, BATCH), 256, conv_smem>>>(x, Wc, bc);
    attn3x3_kernel<<<BATCH * HW / 8, 256>>>(out);
}

// round 3
// speedup vs baseline: 4.0190x; 1.0500x over previous
#include <cuda_runtime.h>
#include <cuda_bf16.h>

// Problem constants
#define BATCH 8
#define CI    64
#define CO    128
#define HH    128
#define WW    128
#define HW    (HH*WW)          // 16384

// Scratch: y = conv1x1(x), PIXEL-MAJOR layout: y[b][p][c], p=h*W+w. 64 MiB fp32.
__device__ float g_y[BATCH * HW * CO];

// ---- packed f32x2 helpers (Blackwell FFMA2) --------------------------------
__device__ __forceinline__ unsigned long long pk2(float a, float b) {
    unsigned long long r;
    asm("mov.b64 %0, {%1, %2};" : "=l"(r) : "f"(a), "f"(b));
    return r;
}
__device__ __forceinline__ void fma2(unsigned long long& d,
                                     unsigned long long a,
                                     unsigned long long b) {
    asm("fma.rn.f32x2 %0, %1, %2, %0;" : "+l"(d) : "l"(a), "l"(b));
}
__device__ __forceinline__ void upk2(float& a, float& b, unsigned long long v) {
    asm("mov.b64 {%0, %1}, %2;" : "=f"(a), "=f"(b) : "l"(v));
}

// ---------------------------------------------------------------------------
// Kernel 1: 1x1 conv as GEMM with packed fp32x2 FMA.
// Per CTA: 128 output channels x 128 pixels. blockDim=256.
// tx (0..15) = channel group, ty (0..15) = pixel group (8 px each).
// Accumulators are pixel-PAIRS packed in 64-bit regs: acc2[4 px-pairs][8 ch].
// ---------------------------------------------------------------------------
__global__ void conv1x1_kernel(const float* __restrict__ x,
                               const float* __restrict__ Wc,
                               const float* __restrict__ bc)
{
    extern __shared__ float sm[];
    float* Ws = sm;            // [i][o] 64*128 (Wc transposed)
    float* Xs = sm + 64 * 128; // [i][p] 64*128

    const int b  = blockIdx.y;
    const int p0 = blockIdx.x * 128;
    const int tid = threadIdx.x;

    for (int idx = tid; idx < 64 * 128; idx += 256) {
        int i = idx >> 7;
        int o = idx & 127;
        Ws[idx] = Wc[o * CI + i];
    }
    {
        const float4* xb4 = reinterpret_cast<const float4*>(x + (size_t)b * CI * HW);
        float4* Xs4 = reinterpret_cast<float4*>(Xs);
        for (int idx = tid; idx < 2048; idx += 256) {
            int i  = idx >> 5;
            int p4 = idx & 31;
            Xs4[idx] = xb4[i * (HW / 4) + (p0 >> 2) + p4];
        }
    }
    __syncthreads();

    const int tx = tid & 15;   // channel group
    const int ty = tid >> 4;   // pixel group

    unsigned long long acc2[4][8];
#pragma unroll
    for (int q = 0; q < 4; ++q)
#pragma unroll
        for (int k = 0; k < 8; ++k) acc2[q][k] = 0ull;

    const float4* Ws4 = reinterpret_cast<const float4*>(Ws);
    const float4* Xs4 = reinterpret_cast<const float4*>(Xs);

#pragma unroll 4
    for (int i = 0; i < 64; ++i) {
        float4 w0 = Ws4[i * 32 + tx];         // channels tx*4..+3
        float4 w1 = Ws4[i * 32 + 16 + tx];    // channels 64+tx*4..+3
        float4 v0 = Xs4[i * 32 + ty * 2];     // pixels ty*8..+3
        float4 v1 = Xs4[i * 32 + ty * 2 + 1]; // pixels ty*8+4..+7

        unsigned long long xp[4];
        xp[0] = pk2(v0.x, v0.y); xp[1] = pk2(v0.z, v0.w);
        xp[2] = pk2(v1.x, v1.y); xp[3] = pk2(v1.z, v1.w);

        unsigned long long wd[8];
        wd[0] = pk2(w0.x, w0.x); wd[1] = pk2(w0.y, w0.y);
        wd[2] = pk2(w0.z, w0.z); wd[3] = pk2(w0.w, w0.w);
        wd[4] = pk2(w1.x, w1.x); wd[5] = pk2(w1.y, w1.y);
        wd[6] = pk2(w1.z, w1.z); wd[7] = pk2(w1.w, w1.w);

#pragma unroll
        for (int q = 0; q < 4; ++q)
#pragma unroll
            for (int k = 0; k < 8; ++k)
                fma2(acc2[q][k], xp[q], wd[k]);
    }

    // Bias
    float bv[8];
#pragma unroll
    for (int k = 0; k < 4; ++k) {
        bv[k]     = bc[tx * 4 + k];
        bv[k + 4] = bc[64 + tx * 4 + k];
    }

    // Write y pixel-major: y[(b*HW + p)*128 + c]
    float* yb = g_y + ((size_t)b * HW + p0) * CO;
#pragma unroll
    for (int q = 0; q < 4; ++q) {      // pixel pair q: pixels 2q, 2q+1 of this thread
        float e[2][8];
#pragma unroll
        for (int k = 0; k < 8; ++k) {
            float lo, hi;
            upk2(lo, hi, acc2[q][k]);
            e[0][k] = lo + bv[k];
            e[1][k] = hi + bv[k];
        }
#pragma unroll
        for (int half = 0; half < 2; ++half) {
            float* dst = yb + (size_t)(ty * 8 + q * 2 + half) * CO;
            float4 r0 = make_float4(e[half][0], e[half][1], e[half][2], e[half][3]);
            float4 r1 = make_float4(e[half][4], e[half][5], e[half][6], e[half][7]);
            reinterpret_cast<float4*>(dst + tx * 4)[0]      = r0;
            reinterpret_cast<float4*>(dst + 64 + tx * 4)[0] = r1;
        }
    }
}

// ---------------------------------------------------------------------------
// Kernel 2: 3x3 local attention, warp per 1x4 pixel strip, register resident.
// CTA = 256 threads = 8 warps = 32 consecutive pixels in one image row.
// Warp loads its 3x6 neighborhood once (18 LDG.128), reuses it for both the
// score pass and the weighted-sum pass.  Lane l owns channels 4l..4l+3.
// ---------------------------------------------------------------------------
__global__ void __launch_bounds__(256) attn3x3_kernel(float* __restrict__ out)
{
    __shared__ float so[32 * CO];  // [pix][c]

    const int tid  = threadIdx.x;
    const int wid  = tid >> 5;
    const int lane = tid & 31;

    const int g32 = blockIdx.x * 32;      // first pixel of CTA
    const int b   = g32 >> 14;            // / HW
    const int p   = g32 & (HW - 1);
    const int h   = p >> 7;               // row (CTA spans one row segment)
    const int wc  = p & (WW - 1);         // CTA col start (multiple of 32)
    const int w0  = wc + wid * 4;         // this warp's first pixel col

    const float* ybase = g_y + ((size_t)b * HW) * CO + lane * 4;

    // Load 3x6 neighborhood (rows h-1..h+1, cols w0-1..w0+4)
    float4 v[3][6];
#pragma unroll
    for (int r = 0; r < 3; ++r) {
        int gh = h - 1 + r;
#pragma unroll
        for (int c = 0; c < 6; ++c) {
            int gw = w0 - 1 + c;
            if ((unsigned)gh < HH && (unsigned)gw < WW) {
                v[r][c] = *reinterpret_cast<const float4*>(
                    ybase + (size_t)(gh * WW + gw) * CO);
            } else {
                v[r][c] = make_float4(0.f, 0.f, 0.f, 0.f);
            }
        }
    }

    const float scale = 0.08838834764831845f; // 1/sqrt(128)

#pragma unroll
    for (int j = 0; j < 4; ++j) {          // pixel within strip
        const float4 mid = v[1][j + 1];

        float s[9];
#pragma unroll
        for (int n = 0; n < 9; ++n) {
            const float4 q = v[n / 3][j + n % 3];
            s[n] = q.x * mid.x + q.y * mid.y + q.z * mid.z + q.w * mid.w;
        }

        // Butterfly all-reduce of 9 scores
#pragma unroll
        for (int off = 16; off > 0; off >>= 1) {
#pragma unroll
            for (int n = 0; n < 9; ++n)
                s[n] += __shfl_xor_sync(0xffffffffu, s[n], off);
        }

        float mx = s[0];
#pragma unroll
        for (int n = 1; n < 9; ++n) mx = fmaxf(mx, s[n]);
        float a[9], den = 0.f;
#pragma unroll
        for (int n = 0; n < 9; ++n) {
            a[n] = __expf((s[n] - mx) * scale);
            den += a[n];
        }
        float inv = 1.0f / den;

        float4 o = make_float4(0.f, 0.f, 0.f, 0.f);
#pragma unroll
        for (int n = 0; n < 9; ++n) {
            const float4 q = v[n / 3][j + n % 3];
            float an = a[n] * inv;
            o.x = fmaf(an, q.x, o.x);
            o.y = fmaf(an, q.y, o.y);
            o.z = fmaf(an, q.z, o.z);
            o.w = fmaf(an, q.w, o.w);
        }

        *reinterpret_cast<float4*>(&so[(wid * 4 + j) * CO + lane * 4]) = o;
    }
    __syncthreads();

    // Transposed, channel-major store.
    // Thread t: channel c = t>>1, pixel quads q = (t&1)*4 + 0..3 (4 px each).
    {
        const int c  = tid >> 1;
        const int qb = (tid & 1) * 4;
        float* dst = out + ((size_t)b * CO + c) * HW + h * WW + wc;
#pragma unroll
        for (int j = 0; j < 4; ++j) {
            int q = qb + j;
            float4 r;
            r.x = so[(q * 4 + 0) * CO + c];
            r.y = so[(q * 4 + 1) * CO + c];
            r.z = so[(q * 4 + 2) * CO + c];
            r.w = so[(q * 4 + 3) * CO + c];
            *reinterpret_cast<float4*>(dst + q * 4) = r;
        }
    }
}

// ---------------------------------------------------------------------------
extern "C" void kernel_launch(void* const* d_in, const int* in_sizes, int n_in,
                              void* d_out, int out_size)
{
    const float* x  = nullptr;
    const float* Wc = nullptr;
    const float* bc = nullptr;
    for (int i = 0; i < n_in; ++i) {
        if (in_sizes[i] == BATCH * CI * HW) x  = (const float*)d_in[i];
        else if (in_sizes[i] == CO * CI)    Wc = (const float*)d_in[i];
        else if (in_sizes[i] == CO)         bc = (const float*)d_in[i];
    }
    float* out = (float*)d_out;

    static const int conv_smem = 64 * 128 * 2 * sizeof(float);   // 65536

    cudaFuncSetAttribute(conv1x1_kernel,
                         cudaFuncAttributeMaxDynamicSharedMemorySize, conv_smem);

    conv1x1_kernel<<<dim3(HW / 128, BATCH), 256, conv_smem>>>(x, Wc, bc);
    attn3x3_kernel<<<BATCH * HW / 32, 256>>>(out);
}